// round 5
// baseline (speedup 1.0000x reference)
#include <cuda_runtime.h>
#include <cstdint>

#define NMAPS   7
#define KPTS    768
#define WIDTH   1024
#define MAPPIX  (WIDTH * WIDTH)
#define KK      (KPTS * KPTS)                 // 589824
#define PLANE   ((size_t)NMAPS * KK)          // 4128768

#define NI 512                                // interleave blocks per map (2048 px each)
#define NS 6                                  // setup blocks per map (128 pts each)
#define NP 384                                // pair blocks per map (2 rows each)
#define BPM (NI + NS + NP)                    // 902 blocks per map

// Interleaved PAF: g_pafi[m][y][x] = (PAF[m][0][y][x], PAF[m][1][y][x])
__device__ float2 g_pafi[NMAPS * MAPPIX];
// Endpoint tables: {x, y, paf_m(p).x, paf_m(p).y}
__device__ float4 g_p1e[NMAPS * KPTS];
__device__ float4 g_p2e[NMAPS * KPTS];
// Pipeline flags (reset every launch by init_kernel)
__device__ int g_cnt_i[NMAPS];
__device__ int g_cnt_s[NMAPS];

__global__ void init_kernel() {
    if (threadIdx.x < NMAPS) {
        g_cnt_i[threadIdx.x] = 0;
        g_cnt_s[threadIdx.x] = 0;
    }
}

__global__ __launch_bounds__(128) void fused_kernel(const int* __restrict__ skel,
                                                    const float* __restrict__ paf,
                                                    float* __restrict__ out) {
    int g   = blockIdx.x;
    int m   = g / BPM;
    int rem = g - m * BPM;
    int t   = threadIdx.x;

    if (rem < NI) {
        // ---- Stage 1: interleave 2048 px of map m (512 quads/block) ----
        int qbase = rem * 512;
        const float4* pa = (const float4*)(paf + (size_t)(2 * m)     * MAPPIX);
        const float4* pb = (const float4*)(paf + (size_t)(2 * m + 1) * MAPPIX);
        float4* dst = (float4*)(g_pafi + (size_t)m * MAPPIX);
#pragma unroll
        for (int u = 0; u < 4; u++) {
            int q = qbase + u * 128 + t;
            float4 a = __ldg(&pa[q]);
            float4 b = __ldg(&pb[q]);
            dst[2 * q]     = make_float4(a.x, b.x, a.y, b.y);
            dst[2 * q + 1] = make_float4(a.z, b.z, a.w, b.w);
        }
        __threadfence();
        __syncthreads();
        if (t == 0) atomicAdd(&g_cnt_i[m], 1);

    } else if (rem < NI + NS) {
        // ---- Stage 2: endpoint tables for map m ----
        if (t == 0) { while (atomicAdd(&g_cnt_i[m], 0) < NI) __nanosleep(64); }
        __syncthreads();
        __threadfence();
        int p = (rem - NI) * 128 + t;                 // 0..767
        const float2* pafm = g_pafi + (size_t)m * MAPPIX;
        int x1 = skel[(m * KPTS + p) * 3 + 1];
        int y1 = skel[(m * KPTS + p) * 3 + 2];
        float2 e1 = pafm[y1 * WIDTH + x1];
        g_p1e[m * KPTS + p] = make_float4((float)x1, (float)y1, e1.x, e1.y);
        int x2 = skel[((m + 1) * KPTS + p) * 3 + 1];
        int y2 = skel[((m + 1) * KPTS + p) * 3 + 2];
        float2 e2 = pafm[y2 * WIDTH + x2];
        g_p2e[m * KPTS + p] = make_float4((float)x2, (float)y2, e2.x, e2.y);
        __threadfence();
        __syncthreads();
        if (t == 0) atomicAdd(&g_cnt_s[m], 1);

    } else {
        // ---- Stage 3: pair costs. 2 rows/block; thread t: r = rt*2 + t/64, c = (t&63)+64k ----
        int rt = rem - NI - NS;
        if (t == 0) { while (atomicAdd(&g_cnt_s[m], 0) < NS) __nanosleep(64); }
        __syncthreads();
        __threadfence();

        int r  = rt * 2 + (t >> 6);
        int c0 = t & 63;

        const float4* __restrict__ p1tab = g_p1e + m * KPTS;
        float4 Q = __ldg(&g_p2e[m * KPTS + r]);
        float p2xf = Q.x, p2yf = Q.y;

        // pre[i] = p2 * ((i+1)/9) + 0.55 ; interior sample x = i+1
        float prex[8], prey[8];
#pragma unroll
        for (int i = 0; i < 8; i++) {
            float cc = (float)((i + 1) / 9.0);
            prex[i] = fmaf(p2xf, cc, 0.55f);
            prey[i] = fmaf(p2yf, cc, 0.55f);
        }

        // floor trick yields (coord+1) per dim; fold into base: -(1024 + 1)
        const float2* __restrict__ pafm_adj = g_pafi + (size_t)m * MAPPIX - 1025;

        size_t base  = (size_t)m * KK + (size_t)r * KPTS;
        float  i2val = (float)((m + 1) * KPTS + r);

#pragma unroll 1
        for (int k = 0; k < 12; k++) {
            int c = c0 + 64 * k;
            float4 P = __ldg(&p1tab[c]);
            float sx = P.z + Q.z;      // exact endpoints x=0, x=9
            float sy = P.w + Q.w;
#pragma unroll
            for (int i = 0; i < 8; i++) {
                float C1 = (float)((8 - i) / 9.0);
                float mx = fmaf(P.x, C1, prex[i]);
                float my = fmaf(P.y, C1, prey[i]);
                int lxb = __float_as_int(mx + 8388608.f) & 0x7FF;   // floor+1
                int lyb = __float_as_int(my + 8388608.f) & 0x7FF;
                float2 v = __ldg(&pafm_adj[lyb * WIDTH + lxb]);
                sx += v.x;
                sy += v.y;
            }
            float dx = p2xf - P.x;
            float dy = p2yf - P.y;
            float R2 = fmaf(dx, dx, dy * dy);
            float Rv = sqrtf(R2);
            float inv = (R2 > 0.f) ? (0.1f / Rv) : 0.f;   // NaN (R==0) -> 0
            float li = (dx * sx + dy * sy) * inv;

            size_t pos = base + c;
            out[pos]             = (float)(m * KPTS + c);  // i1
            out[PLANE + pos]     = i2val;                  // i2
            out[2 * PLANE + pos] = li;                     // cost
            out[3 * PLANE + pos] = Rv;                     // R
        }
    }
}

extern "C" void kernel_launch(void* const* d_in, const int* in_sizes, int n_in,
                              void* d_out, int out_size) {
    const int*   skel;
    const float* paf;
    // skeletons = 6144*3 = 18432 elems; PAF = 7*2*1024*1024 = 14680064 elems
    if (in_sizes[0] < in_sizes[1]) {
        skel = (const int*)d_in[0];
        paf  = (const float*)d_in[1];
    } else {
        skel = (const int*)d_in[1];
        paf  = (const float*)d_in[0];
    }

    init_kernel<<<1, 32>>>();
    fused_kernel<<<NMAPS * BPM, 128>>>(skel, paf, (float*)d_out);
}